// round 9
// baseline (speedup 1.0000x reference)
#include <cuda_runtime.h>
#include <math.h>

#define BGRAPH 128
#define NPG    512
#define NNODES (BGRAPH*NPG)
#define EPG    (NPG*16)
#define NEDGE  (NNODES*16)
#define NT     1024
#define NW     32

// cross-kernel scratch
__device__ float g_u[2][3][BGRAPH*640];
__device__ float g_part[BGRAPH][96];

// SMEM byte offsets for k_fused
#define OFF_XBUF 0          // 512*64 f = 131072
#define OFF_YBUF 131072     // 512*32 f =  65536 (src/dst ushort cache during build; X staging after)
#define OFF_CSR  196608     // ushort[9728] = 19456
#define OFF_OFFS 216064     // ushort[513] -> 1032
#define OFF_INV  217096     // float[512] = 2048
#define OFF_PAD  219144     // uchar[512] = 512
#define OFF_SCR  219656     // int[1040] = 4160
#define SMEM_BYTES 223816

// ---------------- XW stage from SMEM ----------------
template<int FI, int FO, int R>
__device__ __forceinline__ void xw_stage(
    const float* __restrict__ Xs, int xstride, int row0, int nrows,
    float* __restrict__ Ys, const float* __restrict__ W,
    const float* __restrict__ invsh, int warp, int lane)
{
    const int c0 = lane & (FO - 1);
    for (int grp = warp; grp < nrows / R; grp += NW) {
        int r0 = grp * R;
        float acc0[R], acc1[R];
        #pragma unroll
        for (int r = 0; r < R; r++) { acc0[r] = 0.f; acc1[r] = 0.f; }
        #pragma unroll 4
        for (int k = 0; k < FI; k += 4) {
            float w0[4], w1[4];
            #pragma unroll
            for (int q = 0; q < 4; q++) {
                w0[q] = __ldg(W + (k + q) * FO + c0);
                if (FO == 64) w1[q] = __ldg(W + (k + q) * FO + c0 + 32);
            }
            #pragma unroll
            for (int r = 0; r < R; r++) {
                const float4 xv = *(const float4*)(Xs + (r0 + r) * xstride + k);
                acc0[r] = fmaf(xv.x, w0[0], acc0[r]);
                acc0[r] = fmaf(xv.y, w0[1], acc0[r]);
                acc0[r] = fmaf(xv.z, w0[2], acc0[r]);
                acc0[r] = fmaf(xv.w, w0[3], acc0[r]);
                if (FO == 64) {
                    acc1[r] = fmaf(xv.x, w1[0], acc1[r]);
                    acc1[r] = fmaf(xv.y, w1[1], acc1[r]);
                    acc1[r] = fmaf(xv.z, w1[2], acc1[r]);
                    acc1[r] = fmaf(xv.w, w1[3], acc1[r]);
                }
            }
        }
        #pragma unroll
        for (int r = 0; r < R; r++) {
            int n = row0 + r0 + r;
            float inv = invsh[n];
            if (FO >= 32 || lane < FO) Ys[n * FO + c0] = acc0[r] * inv;
            if (FO == 64)              Ys[n * FO + c0 + 32] = acc1[r] * inv;
        }
    }
}

// ---------------- aggregation FO=32, two-node interleaved ----------------
__device__ __forceinline__ void agg32(
    const float* __restrict__ Ys, float* __restrict__ Out,
    const ushort4* __restrict__ csr4, const unsigned short* __restrict__ offsh,
    const float* __restrict__ invsh, const unsigned char* __restrict__ padsh,
    const float* __restrict__ bias, int warp, int lane)
{
    const float b0 = __ldg(bias + lane);
    #pragma unroll
    for (int it = 0; it < 8; it++) {
        int na = warp + it * NW;
        int nb = na + 256;
        int qa = offsh[na] >> 2;
        int la = (offsh[na + 1] >> 2) - qa;
        int qb = offsh[nb] >> 2;
        int lb = (offsh[nb + 1] >> 2) - qb;
        float a = 0.f, b = 0.f;
        int cmin = la < lb ? la : lb;
        for (int t = 0; t < cmin; t++) {
            ushort4 ia = csr4[qa + t];
            ushort4 ib = csr4[qb + t];
            a += Ys[ia.x * 32 + lane];  b += Ys[ib.x * 32 + lane];
            a += Ys[ia.y * 32 + lane];  b += Ys[ib.y * 32 + lane];
            a += Ys[ia.z * 32 + lane];  b += Ys[ib.z * 32 + lane];
            a += Ys[ia.w * 32 + lane];  b += Ys[ib.w * 32 + lane];
        }
        for (int t = cmin; t < la; t++) {
            ushort4 ia = csr4[qa + t];
            a += Ys[ia.x * 32 + lane];
            a += Ys[ia.y * 32 + lane];
            a += Ys[ia.z * 32 + lane];
            a += Ys[ia.w * 32 + lane];
        }
        for (int t = cmin; t < lb; t++) {
            ushort4 ib = csr4[qb + t];
            b += Ys[ib.x * 32 + lane];
            b += Ys[ib.y * 32 + lane];
            b += Ys[ib.z * 32 + lane];
            b += Ys[ib.w * 32 + lane];
        }
        float ca = 1.f - (float)padsh[na];
        a = fmaf(ca, Ys[na * 32 + lane], a);
        Out[na * 32 + lane] = fmaxf(a * invsh[na] + b0, 0.f);
        float cb = 1.f - (float)padsh[nb];
        b = fmaf(cb, Ys[nb * 32 + lane], b);
        Out[nb * 32 + lane] = fmaxf(b * invsh[nb] + b0, 0.f);
    }
}

// ---------------- resize-tap projection ----------------
template<int FO>
__device__ __forceinline__ void taps(const float* __restrict__ Hs, int stride,
                                     float* __restrict__ uout, int tid)
{
    for (int t = tid; t < 10 * FO; t += NT) {
        int p = t / FO, d = t % FO;
        float c = (p + 0.5f) * 51.2f - 0.5f;
        int i0 = (int)floorf(c);
        float w = c - (float)i0;
        uout[p * 64 + d] = Hs[i0 * stride + d] * (1.f - w) + Hs[(i0 + 1) * stride + d] * w;
    }
}

// ---------------- fused per-(graph,side) kernel ----------------
__global__ void __launch_bounds__(NT, 1)
k_fused(const float* __restrict__ x0, const float* __restrict__ x1,
        const float* __restrict__ W0, const float* __restrict__ b0,
        const float* __restrict__ W1, const float* __restrict__ b1,
        const float* __restrict__ W2, const float* __restrict__ b2,
        const int* __restrict__ ei, const int* __restrict__ ej)
{
    extern __shared__ char smraw[];
    float*          xbuf  = (float*)(smraw + OFF_XBUF);
    float*          ybuf  = (float*)(smraw + OFF_YBUF);
    unsigned short* csr   = (unsigned short*)(smraw + OFF_CSR);
    const ushort4*  csr4  = (const ushort4*)csr;
    unsigned short* offsh = (unsigned short*)(smraw + OFF_OFFS);
    float*          invsh = (float*)(smraw + OFF_INV);
    unsigned char*  padsh = (unsigned char*)(smraw + OFF_PAD);
    int*            cnt   = (int*)(smraw + OFF_SCR);   // [512]
    int*            cur   = cnt + 512;                 // [512]
    int*            wtot  = cnt + 1024;                // [16]

    const int side = blockIdx.y, g = blockIdx.x;
    const int tid = threadIdx.x, warp = tid >> 5, lane = tid & 31;
    const int* E    = side ? ej : ei;
    const int* esrc = E + g * EPG;
    const int* edst = E + NEDGE + g * EPG;
    const float* Xg = (side ? x1 : x0) + (size_t)g * NPG * 64;

    // ---- count pass: cache src/dst into ybuf as ushort, count degrees ----
    unsigned short* srcc = (unsigned short*)ybuf;   // [8192]
    unsigned short* dstc = srcc + EPG;              // [8192]
    if (tid < 512) cnt[tid] = 0;
    __syncthreads();
    for (int e = tid; e < EPG; e += NT) {
        int sv = esrc[e] & (NPG - 1), dv = edst[e] & (NPG - 1);
        srcc[e] = (unsigned short)sv;
        dstc[e] = (unsigned short)dv;
        atomicAdd(&cnt[dv], 1);
    }
    __syncthreads();

    // ---- scan of padded degrees ----
    int deg = 0, pc = 0, s_incl = 0, off = 0;
    if (tid < 512) {
        deg = cnt[tid];
        pc  = (deg + 3) & ~3;
        s_incl = pc;
        #pragma unroll
        for (int d = 1; d < 32; d <<= 1) {
            int v = __shfl_up_sync(0xffffffffu, s_incl, d);
            if (lane >= d) s_incl += v;
        }
        if (lane == 31) wtot[warp] = s_incl;
    }
    __syncthreads();
    if (tid < 16) {
        int t = wtot[tid];
        #pragma unroll
        for (int d = 1; d < 16; d <<= 1) {
            int v = __shfl_up_sync(0x0000ffffu, t, d);
            if (tid >= d) t += v;
        }
        wtot[tid] = t;
    }
    __syncthreads();
    if (tid < 512) {
        int base = warp ? wtot[warp - 1] : 0;
        off = base + s_incl - pc;
        offsh[tid] = (unsigned short)off;
        if (tid == 511) offsh[512] = (unsigned short)(off + pc);
        invsh[tid] = rsqrtf((float)deg + 1.0f);
        padsh[tid] = (unsigned char)(pc - deg);
        cur[tid] = off;
    }
    __syncthreads();

    // ---- fill pass: SMEM only ----
    for (int e = tid; e < EPG; e += NT) {
        int dv = dstc[e];
        int p = atomicAdd(&cur[dv], 1);
        csr[p] = srcc[e];
    }
    if (tid < 512)
        for (int t = deg; t < pc; t++) csr[off + t] = (unsigned short)tid;
    __syncthreads();

    // ---- layer 0 XW: stage X through ybuf in two 256-row chunks ----
    for (int ch = 0; ch < 2; ch++) {
        const float4* src = (const float4*)(Xg + (size_t)ch * 256 * 64);
        float4* dst = (float4*)ybuf;
        for (int i = tid; i < 4096; i += NT) dst[i] = src[i];
        __syncthreads();
        xw_stage<64, 64, 8>(ybuf, 64, ch * 256, 256, xbuf, W0, invsh, warp, lane);
        __syncthreads();
    }

    // ---- agg0: gather xbuf with next-quad prefetch, stage in regs, write back ----
    {
        float h0[16], h1[16];
        const float bb0 = __ldg(b0 + lane);
        const float bb1 = __ldg(b0 + lane + 32);
        #pragma unroll
        for (int it = 0; it < 16; it++) {
            int n = warp + it * NW;
            int q0 = offsh[n] >> 2, q1 = offsh[n + 1] >> 2;
            float a0 = 0.f, a1 = 0.f;
            ushort4 ix = csr4[q0];
            for (int q = q0; q < q1; q++) {
                ushort4 cu = ix;
                ix = csr4[q + 1];          // prefetch (1-past read stays in SMEM, unused)
                a0 += xbuf[cu.x * 64 + lane];  a1 += xbuf[cu.x * 64 + lane + 32];
                a0 += xbuf[cu.y * 64 + lane];  a1 += xbuf[cu.y * 64 + lane + 32];
                a0 += xbuf[cu.z * 64 + lane];  a1 += xbuf[cu.z * 64 + lane + 32];
                a0 += xbuf[cu.w * 64 + lane];  a1 += xbuf[cu.w * 64 + lane + 32];
            }
            float corr = 1.f - (float)padsh[n];
            a0 = fmaf(corr, xbuf[n * 64 + lane], a0);
            a1 = fmaf(corr, xbuf[n * 64 + lane + 32], a1);
            float inv = invsh[n];
            h0[it] = fmaxf(a0 * inv + bb0, 0.f);
            h1[it] = fmaxf(a1 * inv + bb1, 0.f);
        }
        __syncthreads();
        #pragma unroll
        for (int it = 0; it < 16; it++) {
            int n = warp + it * NW;
            xbuf[n * 64 + lane] = h0[it];
            xbuf[n * 64 + lane + 32] = h1[it];
        }
        __syncthreads();
    }

    // ---- taps0 + XW1 (R=16: one group per warp) ----
    taps<64>(xbuf, 64, &g_u[side][0][g * 640], tid);
    xw_stage<64, 32, 16>(xbuf, 64, 0, NPG, ybuf, W1, invsh, warp, lane);
    __syncthreads();

    // ---- agg1: ybuf -> xbuf (two-node interleaved) ----
    agg32(ybuf, xbuf, csr4, offsh, invsh, padsh, b1, warp, lane);
    __syncthreads();

    // ---- taps1 + XW2 (R=16) ----
    taps<32>(xbuf, 32, &g_u[side][1][g * 640], tid);
    xw_stage<32, 16, 16>(xbuf, 32, 0, NPG, ybuf, W2, invsh, warp, lane);
    __syncthreads();

    // ---- fused agg2 + taps2: only the 20 tap rows ----
    float* tmp = (float*)cnt;
    if (warp < 20) {
        int p = warp >> 1;
        float c = (p + 0.5f) * 51.2f - 0.5f;
        int i0 = (int)floorf(c);
        int r = i0 + (warp & 1);
        int c0 = lane & 15;
        int q0 = offsh[r] >> 2, q1 = offsh[r + 1] >> 2;
        float a = 0.f;
        for (int q = q0; q < q1; q++) {
            ushort4 ix = csr4[q];
            a += ybuf[ix.x * 16 + c0];
            a += ybuf[ix.y * 16 + c0];
            a += ybuf[ix.z * 16 + c0];
            a += ybuf[ix.w * 16 + c0];
        }
        a = fmaf(1.f - (float)padsh[r], ybuf[r * 16 + c0], a);
        tmp[warp * 16 + c0] = a * invsh[r] + __ldg(b2 + c0);
    }
    __syncthreads();
    if (tid < 160) {
        int p = tid >> 4, d = tid & 15;
        float c = (p + 0.5f) * 51.2f - 0.5f;
        int i0 = (int)floorf(c);
        float w = c - (float)i0;
        g_u[side][2][g * 640 + p * 64 + d] =
            tmp[(2 * p) * 16 + d] * (1.f - w) + tmp[(2 * p + 1) * 16 + d] * w;
    }
}

// ---------------- headA: per (graph,layer): sim + conv + partial MLP0 ----------------
__global__ void __launch_bounds__(256)
k_headA(const float* __restrict__ cw0, const float* __restrict__ cb0,
        const float* __restrict__ cw1, const float* __restrict__ cb1,
        const float* __restrict__ cw2, const float* __restrict__ cb2,
        const float* __restrict__ mw0)
{
    int b = blockIdx.x, l = blockIdx.y;
    int tid = threadIdx.x, warp = tid >> 5, lane = tid & 31;
    __shared__ float ui[640], uj[640];
    __shared__ float sim[100];
    __shared__ float feat[800];
    __shared__ float cwsm[72], cbsm[8];
    __shared__ float red[8][32];

    for (int t = tid; t < 640; t += 256) {
        ui[t] = g_u[0][l][b*640 + t];
        uj[t] = g_u[1][l][b*640 + t];
    }
    const float* cw = (l==0) ? cw0 : (l==1) ? cw1 : cw2;
    const float* cb = (l==0) ? cb0 : (l==1) ? cb1 : cb2;
    if (tid < 72) cwsm[tid] = __ldg(cw + tid);
    if (tid >= 128 && tid < 136) cbsm[tid-128] = __ldg(cb + tid - 128);
    __syncthreads();

    const int fo = 64 >> l;
    for (int ent = warp; ent < 100; ent += 8) {
        int p = ent / 10, q = ent % 10;
        float s = 0.f;
        for (int d = lane; d < fo; d += 32)
            s = fmaf(ui[p*64 + d], uj[q*64 + d], s);
        #pragma unroll
        for (int o = 16; o; o >>= 1) s += __shfl_xor_sync(0xffffffffu, s, o);
        if (lane == 0) sim[ent] = s;
    }
    __syncthreads();

    for (int t = tid; t < 800; t += 256) {
        int ch = t / 100, rc = t % 100, r = rc / 10, c = rc % 10;
        float acc = cbsm[ch];
        #pragma unroll
        for (int dr = 0; dr < 3; dr++)
            #pragma unroll
            for (int dc = 0; dc < 3; dc++) {
                int rr = r + dr - 1, cc = c + dc - 1;
                if (rr >= 0 && rr < 10 && cc >= 0 && cc < 10)
                    acc = fmaf(cwsm[ch*9 + dr*3 + dc], sim[rr*10 + cc], acc);
            }
        feat[t] = fmaxf(acc, 0.f);
    }
    __syncthreads();

    {
        int o = lane, part = warp;
        const float* w0 = mw0 + (size_t)l * 800 * 32;
        float acc = 0.f;
        #pragma unroll 5
        for (int k = part; k < 800; k += 8)
            acc = fmaf(feat[k], __ldg(w0 + k*32 + o), acc);
        red[part][o] = acc;
    }
    __syncthreads();
    if (tid < 32) {
        float s = 0.f;
        #pragma unroll
        for (int p = 0; p < 8; p++) s += red[p][tid];
        g_part[b][l*32 + tid] = s;
    }
}

// ---------------- headB: warp per graph: sum partials + MLP tail + sigmoid ----------------
__global__ void __launch_bounds__(1024)
k_headB(const float* __restrict__ mb0,
        const float* __restrict__ mw1, const float* __restrict__ mb1,
        const float* __restrict__ mw2, const float* __restrict__ mb2,
        const float* __restrict__ mw3, const float* __restrict__ mb3,
        const float* __restrict__ mw4, const float* __restrict__ mb4,
        const float* __restrict__ sw,  const float* __restrict__ sb,
        float* __restrict__ out)
{
    int b = (blockIdx.x * 1024 + threadIdx.x) >> 5;
    int lane = threadIdx.x & 31;
    if (b >= BGRAPH) return;

    float s = __ldg(mb0 + lane) + g_part[b][lane] + g_part[b][32 + lane] + g_part[b][64 + lane];
    float a0 = fmaxf(s, 0.f);

    float a1 = (lane < 16) ? __ldg(mb1 + lane) : 0.f;
    #pragma unroll
    for (int k = 0; k < 32; k++) {
        float v = __shfl_sync(0xffffffffu, a0, k);
        if (lane < 16) a1 = fmaf(v, __ldg(mw1 + k*16 + lane), a1);
    }
    a1 = fmaxf(a1, 0.f);

    float a2 = (lane < 8) ? __ldg(mb2 + lane) : 0.f;
    #pragma unroll
    for (int k = 0; k < 16; k++) {
        float v = __shfl_sync(0xffffffffu, a1, k);
        if (lane < 8) a2 = fmaf(v, __ldg(mw2 + k*8 + lane), a2);
    }
    a2 = fmaxf(a2, 0.f);

    float a3 = (lane < 4) ? __ldg(mb3 + lane) : 0.f;
    #pragma unroll
    for (int k = 0; k < 8; k++) {
        float v = __shfl_sync(0xffffffffu, a2, k);
        if (lane < 4) a3 = fmaf(v, __ldg(mw3 + k*4 + lane), a3);
    }
    a3 = fmaxf(a3, 0.f);

    float v0 = __shfl_sync(0xffffffffu, a3, 0);
    float v1 = __shfl_sync(0xffffffffu, a3, 1);
    float v2 = __shfl_sync(0xffffffffu, a3, 2);
    float v3 = __shfl_sync(0xffffffffu, a3, 3);
    if (lane == 0) {
        float s4 = __ldg(mb4);
        s4 = fmaf(v0, __ldg(mw4 + 0), s4);
        s4 = fmaf(v1, __ldg(mw4 + 1), s4);
        s4 = fmaf(v2, __ldg(mw4 + 2), s4);
        s4 = fmaf(v3, __ldg(mw4 + 3), s4);
        float f = fmaxf(s4, 0.f);
        float sc = f * __ldg(sw) + __ldg(sb);
        out[b] = 1.f / (1.f + expf(-sc));
    }
}

// ---------------- launch ----------------
extern "C" void kernel_launch(void* const* d_in, const int* in_sizes, int n_in,
                              void* d_out, int out_size) {
    const float* x_i = (const float*)d_in[0];
    const float* x_j = (const float*)d_in[1];
    const float* gw0 = (const float*)d_in[2];  const float* gb0 = (const float*)d_in[3];
    const float* gw1 = (const float*)d_in[4];  const float* gb1 = (const float*)d_in[5];
    const float* gw2 = (const float*)d_in[6];  const float* gb2 = (const float*)d_in[7];
    const float* cw0 = (const float*)d_in[8];  const float* cb0 = (const float*)d_in[9];
    const float* cw1 = (const float*)d_in[10]; const float* cb1 = (const float*)d_in[11];
    const float* cw2 = (const float*)d_in[12]; const float* cb2 = (const float*)d_in[13];
    const float* mw0 = (const float*)d_in[14]; const float* mb0 = (const float*)d_in[15];
    const float* mw1 = (const float*)d_in[16]; const float* mb1 = (const float*)d_in[17];
    const float* mw2 = (const float*)d_in[18]; const float* mb2 = (const float*)d_in[19];
    const float* mw3 = (const float*)d_in[20]; const float* mb3 = (const float*)d_in[21];
    const float* mw4 = (const float*)d_in[22]; const float* mb4 = (const float*)d_in[23];
    const float* sw  = (const float*)d_in[24]; const float* sb  = (const float*)d_in[25];
    const int*   ei  = (const int*)d_in[26];
    const int*   ej  = (const int*)d_in[27];

    cudaFuncSetAttribute(k_fused, cudaFuncAttributeMaxDynamicSharedMemorySize, SMEM_BYTES);

    k_fused<<<dim3(BGRAPH, 2), NT, SMEM_BYTES>>>(x_i, x_j, gw0, gb0, gw1, gb1, gw2, gb2, ei, ej);
    k_headA<<<dim3(BGRAPH, 3), 256>>>(cw0, cb0, cw1, cb1, cw2, cb2, mw0);
    k_headB<<<(BGRAPH*32 + 1023)/1024, 1024>>>(mb0, mw1, mb1, mw2, mb2, mw3, mb3, mw4, mb4,
                                               sw, sb, (float*)d_out);
}

// round 10
// speedup vs baseline: 1.6332x; 1.6332x over previous
#include <cuda_runtime.h>
#include <math.h>

#define BGRAPH 128
#define NPG    512
#define NNODES (BGRAPH*NPG)
#define EPG    (NPG*16)
#define NEDGE  (NNODES*16)
#define NT     1024
#define NW     32

// cross-kernel scratch
__device__ float g_u[2][3][BGRAPH*640];
__device__ float g_part[BGRAPH][96];

// SMEM byte offsets for k_fused
#define OFF_XBUF 0          // 512*64 f = 131072
#define OFF_YBUF 131072     // 512*32 f =  65536
#define OFF_CSR  196608     // ushort[9728] = 19456
#define OFF_OFFS 216064     // ushort[513] -> 1032
#define OFF_INV  217096     // float[512] = 2048
#define OFF_PAD  219144     // uchar[512] = 512
#define OFF_SCR  219656     // int[1040] = 4160
#define SMEM_BYTES 223816

// ---------------- XW0: FO=64, lane owns column pair (2l, 2l+1), float2 W loads ----------------
template<int R>
__device__ __forceinline__ void xw0_pair(
    const float* __restrict__ Xs, int row0, int nrows,
    float* __restrict__ Ys, const float* __restrict__ W,
    const float* __restrict__ invsh, int warp, int lane)
{
    const int c0 = 2 * lane;
    for (int grp = warp; grp < nrows / R; grp += NW) {
        int r0 = grp * R;
        float a0[R], a1[R];
        #pragma unroll
        for (int r = 0; r < R; r++) { a0[r] = 0.f; a1[r] = 0.f; }
        #pragma unroll 4
        for (int k = 0; k < 64; k += 4) {
            float2 w[4];
            #pragma unroll
            for (int q = 0; q < 4; q++)
                w[q] = __ldg((const float2*)(W + (k + q) * 64 + c0));
            #pragma unroll
            for (int r = 0; r < R; r++) {
                const float4 xv = *(const float4*)(Xs + (r0 + r) * 64 + k);
                a0[r] = fmaf(xv.x, w[0].x, a0[r]);  a1[r] = fmaf(xv.x, w[0].y, a1[r]);
                a0[r] = fmaf(xv.y, w[1].x, a0[r]);  a1[r] = fmaf(xv.y, w[1].y, a1[r]);
                a0[r] = fmaf(xv.z, w[2].x, a0[r]);  a1[r] = fmaf(xv.z, w[2].y, a1[r]);
                a0[r] = fmaf(xv.w, w[3].x, a0[r]);  a1[r] = fmaf(xv.w, w[3].y, a1[r]);
            }
        }
        #pragma unroll
        for (int r = 0; r < R; r++) {
            int n = row0 + r0 + r;
            float inv = invsh[n];
            float2 o; o.x = a0[r] * inv; o.y = a1[r] * inv;
            *(float2*)(Ys + n * 64 + c0) = o;
        }
    }
}

// ---------------- XW stage from SMEM (layers 1,2; scalar cols) ----------------
template<int FI, int FO, int R>
__device__ __forceinline__ void xw_stage(
    const float* __restrict__ Xs, int xstride, int row0, int nrows,
    float* __restrict__ Ys, const float* __restrict__ W,
    const float* __restrict__ invsh, int warp, int lane)
{
    const int c0 = lane & (FO - 1);
    for (int grp = warp; grp < nrows / R; grp += NW) {
        int r0 = grp * R;
        float acc0[R];
        #pragma unroll
        for (int r = 0; r < R; r++) acc0[r] = 0.f;
        #pragma unroll 4
        for (int k = 0; k < FI; k += 4) {
            float w0[4];
            #pragma unroll
            for (int q = 0; q < 4; q++) w0[q] = __ldg(W + (k + q) * FO + c0);
            #pragma unroll
            for (int r = 0; r < R; r++) {
                const float4 xv = *(const float4*)(Xs + (r0 + r) * xstride + k);
                acc0[r] = fmaf(xv.x, w0[0], acc0[r]);
                acc0[r] = fmaf(xv.y, w0[1], acc0[r]);
                acc0[r] = fmaf(xv.z, w0[2], acc0[r]);
                acc0[r] = fmaf(xv.w, w0[3], acc0[r]);
            }
        }
        #pragma unroll
        for (int r = 0; r < R; r++) {
            int n = row0 + r0 + r;
            if (FO >= 32 || lane < FO) Ys[n * FO + c0] = acc0[r] * invsh[n];
        }
    }
}

// ---------------- aggregation FO=32, direct write ----------------
__device__ __forceinline__ void agg32(
    const float* __restrict__ Ys, float* __restrict__ Out,
    const ushort4* __restrict__ csr4, const unsigned short* __restrict__ offsh,
    const float* __restrict__ invsh, const unsigned char* __restrict__ padsh,
    const float* __restrict__ bias, int warp, int lane)
{
    const float b0 = __ldg(bias + lane);
    for (int n = warp; n < NPG; n += NW) {
        int q0 = offsh[n] >> 2, q1 = offsh[n + 1] >> 2;
        float a0 = 0.f;
        for (int q = q0; q < q1; q++) {
            ushort4 ix = csr4[q];
            a0 += Ys[ix.x * 32 + lane];
            a0 += Ys[ix.y * 32 + lane];
            a0 += Ys[ix.z * 32 + lane];
            a0 += Ys[ix.w * 32 + lane];
        }
        float corr = 1.f - (float)padsh[n];
        a0 = fmaf(corr, Ys[n * 32 + lane], a0);
        Out[n * 32 + lane] = fmaxf(a0 * invsh[n] + b0, 0.f);
    }
}

// ---------------- resize-tap projection ----------------
template<int FO>
__device__ __forceinline__ void taps(const float* __restrict__ Hs, int stride,
                                     float* __restrict__ uout, int tid)
{
    for (int t = tid; t < 10 * FO; t += NT) {
        int p = t / FO, d = t % FO;
        float c = (p + 0.5f) * 51.2f - 0.5f;
        int i0 = (int)floorf(c);
        float w = c - (float)i0;
        uout[p * 64 + d] = Hs[i0 * stride + d] * (1.f - w) + Hs[(i0 + 1) * stride + d] * w;
    }
}

// ---------------- fused per-(graph,side) kernel ----------------
__global__ void __launch_bounds__(NT, 1)
k_fused(const float* __restrict__ x0, const float* __restrict__ x1,
        const float* __restrict__ W0, const float* __restrict__ b0,
        const float* __restrict__ W1, const float* __restrict__ b1,
        const float* __restrict__ W2, const float* __restrict__ b2,
        const int* __restrict__ ei, const int* __restrict__ ej)
{
    extern __shared__ char smraw[];
    float*          xbuf  = (float*)(smraw + OFF_XBUF);
    float*          ybuf  = (float*)(smraw + OFF_YBUF);
    unsigned short* csr   = (unsigned short*)(smraw + OFF_CSR);
    const ushort4*  csr4  = (const ushort4*)csr;
    unsigned short* offsh = (unsigned short*)(smraw + OFF_OFFS);
    float*          invsh = (float*)(smraw + OFF_INV);
    unsigned char*  padsh = (unsigned char*)(smraw + OFF_PAD);
    int*            cnt   = (int*)(smraw + OFF_SCR);   // [512]
    int*            cur   = cnt + 512;                 // [512]
    int*            wtot  = cnt + 1024;                // [16]

    const int side = blockIdx.y, g = blockIdx.x;
    const int tid = threadIdx.x, warp = tid >> 5, lane = tid & 31;
    const int* E    = side ? ej : ei;
    const int* esrc = E + g * EPG;
    const int* edst = E + NEDGE + g * EPG;
    const float* Xg = (side ? x1 : x0) + (size_t)g * NPG * 64;

    // ---- count pass: cache src/dst into ybuf as ushort, count degrees ----
    unsigned short* srcc = (unsigned short*)ybuf;   // [8192]
    unsigned short* dstc = srcc + EPG;              // [8192]
    if (tid < 512) cnt[tid] = 0;
    __syncthreads();
    for (int e = tid; e < EPG; e += NT) {
        int sv = esrc[e] & (NPG - 1), dv = edst[e] & (NPG - 1);
        srcc[e] = (unsigned short)sv;
        dstc[e] = (unsigned short)dv;
        atomicAdd(&cnt[dv], 1);
    }
    __syncthreads();

    // ---- scan of padded degrees ----
    int deg = 0, pc = 0, s_incl = 0, off = 0;
    if (tid < 512) {
        deg = cnt[tid];
        pc  = (deg + 3) & ~3;
        s_incl = pc;
        #pragma unroll
        for (int d = 1; d < 32; d <<= 1) {
            int v = __shfl_up_sync(0xffffffffu, s_incl, d);
            if (lane >= d) s_incl += v;
        }
        if (lane == 31) wtot[warp] = s_incl;
    }
    __syncthreads();
    if (tid < 16) {
        int t = wtot[tid];
        #pragma unroll
        for (int d = 1; d < 16; d <<= 1) {
            int v = __shfl_up_sync(0x0000ffffu, t, d);
            if (tid >= d) t += v;
        }
        wtot[tid] = t;
    }
    __syncthreads();
    if (tid < 512) {
        int base = warp ? wtot[warp - 1] : 0;
        off = base + s_incl - pc;
        offsh[tid] = (unsigned short)off;
        if (tid == 511) offsh[512] = (unsigned short)(off + pc);
        invsh[tid] = rsqrtf((float)deg + 1.0f);
        padsh[tid] = (unsigned char)(pc - deg);
        cur[tid] = off;
    }
    __syncthreads();

    // ---- fill pass: SMEM only ----
    for (int e = tid; e < EPG; e += NT) {
        int dv = dstc[e];
        int p = atomicAdd(&cur[dv], 1);
        csr[p] = srcc[e];
    }
    if (tid < 512)
        for (int t = deg; t < pc; t++) csr[off + t] = (unsigned short)tid;
    __syncthreads();

    // ---- layer 0 XW: stage X through ybuf in two 256-row chunks ----
    for (int ch = 0; ch < 2; ch++) {
        const float4* src = (const float4*)(Xg + (size_t)ch * 256 * 64);
        float4* dst = (float4*)ybuf;
        for (int i = tid; i < 4096; i += NT) dst[i] = src[i];
        __syncthreads();
        xw0_pair<8>(ybuf, ch * 256, 256, xbuf, W0, invsh, warp, lane);
        __syncthreads();
    }

    // ---- agg0: gather xbuf, stage in regs, write back ----
    {
        float h0[16], h1[16];
        const float bb0 = __ldg(b0 + lane);
        const float bb1 = __ldg(b0 + lane + 32);
        #pragma unroll
        for (int it = 0; it < 16; it++) {
            int n = warp + it * NW;
            int q0 = offsh[n] >> 2, q1 = offsh[n + 1] >> 2;
            float a0 = 0.f, a1 = 0.f;
            for (int q = q0; q < q1; q++) {
                ushort4 ix = csr4[q];
                a0 += xbuf[ix.x * 64 + lane];  a1 += xbuf[ix.x * 64 + lane + 32];
                a0 += xbuf[ix.y * 64 + lane];  a1 += xbuf[ix.y * 64 + lane + 32];
                a0 += xbuf[ix.z * 64 + lane];  a1 += xbuf[ix.z * 64 + lane + 32];
                a0 += xbuf[ix.w * 64 + lane];  a1 += xbuf[ix.w * 64 + lane + 32];
            }
            float corr = 1.f - (float)padsh[n];
            a0 = fmaf(corr, xbuf[n * 64 + lane], a0);
            a1 = fmaf(corr, xbuf[n * 64 + lane + 32], a1);
            float inv = invsh[n];
            h0[it] = fmaxf(a0 * inv + bb0, 0.f);
            h1[it] = fmaxf(a1 * inv + bb1, 0.f);
        }
        __syncthreads();
        #pragma unroll
        for (int it = 0; it < 16; it++) {
            int n = warp + it * NW;
            xbuf[n * 64 + lane] = h0[it];
            xbuf[n * 64 + lane + 32] = h1[it];
        }
        __syncthreads();
    }

    // ---- taps0 + XW1 ----
    taps<64>(xbuf, 64, &g_u[side][0][g * 640], tid);
    xw_stage<64, 32, 8>(xbuf, 64, 0, NPG, ybuf, W1, invsh, warp, lane);
    __syncthreads();

    // ---- agg1: ybuf -> xbuf ----
    agg32(ybuf, xbuf, csr4, offsh, invsh, padsh, b1, warp, lane);
    __syncthreads();

    // ---- taps1 + XW2 ----
    taps<32>(xbuf, 32, &g_u[side][1][g * 640], tid);
    xw_stage<32, 16, 8>(xbuf, 32, 0, NPG, ybuf, W2, invsh, warp, lane);
    __syncthreads();

    // ---- fused agg2 + taps2: only the 20 tap rows ----
    float* tmp = (float*)cnt;
    if (warp < 20) {
        int p = warp >> 1;
        float c = (p + 0.5f) * 51.2f - 0.5f;
        int i0 = (int)floorf(c);
        int r = i0 + (warp & 1);
        int c0 = lane & 15;
        int q0 = offsh[r] >> 2, q1 = offsh[r + 1] >> 2;
        float a = 0.f;
        for (int q = q0; q < q1; q++) {
            ushort4 ix = csr4[q];
            a += ybuf[ix.x * 16 + c0];
            a += ybuf[ix.y * 16 + c0];
            a += ybuf[ix.z * 16 + c0];
            a += ybuf[ix.w * 16 + c0];
        }
        a = fmaf(1.f - (float)padsh[r], ybuf[r * 16 + c0], a);
        tmp[warp * 16 + c0] = a * invsh[r] + __ldg(b2 + c0);
    }
    __syncthreads();
    if (tid < 160) {
        int p = tid >> 4, d = tid & 15;
        float c = (p + 0.5f) * 51.2f - 0.5f;
        int i0 = (int)floorf(c);
        float w = c - (float)i0;
        g_u[side][2][g * 640 + p * 64 + d] =
            tmp[(2 * p) * 16 + d] * (1.f - w) + tmp[(2 * p + 1) * 16 + d] * w;
    }
}

// ---------------- headA: per (graph,layer): sim + conv + partial MLP0 ----------------
__global__ void __launch_bounds__(256)
k_headA(const float* __restrict__ cw0, const float* __restrict__ cb0,
        const float* __restrict__ cw1, const float* __restrict__ cb1,
        const float* __restrict__ cw2, const float* __restrict__ cb2,
        const float* __restrict__ mw0)
{
    int b = blockIdx.x, l = blockIdx.y;
    int tid = threadIdx.x, warp = tid >> 5, lane = tid & 31;
    __shared__ float ui[640], uj[640];
    __shared__ float sim[100];
    __shared__ float feat[800];
    __shared__ float cwsm[72], cbsm[8];
    __shared__ float red[8][32];

    for (int t = tid; t < 640; t += 256) {
        ui[t] = g_u[0][l][b*640 + t];
        uj[t] = g_u[1][l][b*640 + t];
    }
    const float* cw = (l==0) ? cw0 : (l==1) ? cw1 : cw2;
    const float* cb = (l==0) ? cb0 : (l==1) ? cb1 : cb2;
    if (tid < 72) cwsm[tid] = __ldg(cw + tid);
    if (tid >= 128 && tid < 136) cbsm[tid-128] = __ldg(cb + tid - 128);
    __syncthreads();

    const int fo = 64 >> l;
    for (int ent = warp; ent < 100; ent += 8) {
        int p = ent / 10, q = ent % 10;
        float s = 0.f;
        for (int d = lane; d < fo; d += 32)
            s = fmaf(ui[p*64 + d], uj[q*64 + d], s);
        #pragma unroll
        for (int o = 16; o; o >>= 1) s += __shfl_xor_sync(0xffffffffu, s, o);
        if (lane == 0) sim[ent] = s;
    }
    __syncthreads();

    for (int t = tid; t < 800; t += 256) {
        int ch = t / 100, rc = t % 100, r = rc / 10, c = rc % 10;
        float acc = cbsm[ch];
        #pragma unroll
        for (int dr = 0; dr < 3; dr++)
            #pragma unroll
            for (int dc = 0; dc < 3; dc++) {
                int rr = r + dr - 1, cc = c + dc - 1;
                if (rr >= 0 && rr < 10 && cc >= 0 && cc < 10)
                    acc = fmaf(cwsm[ch*9 + dr*3 + dc], sim[rr*10 + cc], acc);
            }
        feat[t] = fmaxf(acc, 0.f);
    }
    __syncthreads();

    {
        int o = lane, part = warp;
        const float* w0 = mw0 + (size_t)l * 800 * 32;
        float acc = 0.f;
        #pragma unroll 5
        for (int k = part; k < 800; k += 8)
            acc = fmaf(feat[k], __ldg(w0 + k*32 + o), acc);
        red[part][o] = acc;
    }
    __syncthreads();
    if (tid < 32) {
        float s = 0.f;
        #pragma unroll
        for (int p = 0; p < 8; p++) s += red[p][tid];
        g_part[b][l*32 + tid] = s;
    }
}

// ---------------- headB: warp per graph: sum partials + MLP tail + sigmoid ----------------
__global__ void __launch_bounds__(1024)
k_headB(const float* __restrict__ mb0,
        const float* __restrict__ mw1, const float* __restrict__ mb1,
        const float* __restrict__ mw2, const float* __restrict__ mb2,
        const float* __restrict__ mw3, const float* __restrict__ mb3,
        const float* __restrict__ mw4, const float* __restrict__ mb4,
        const float* __restrict__ sw,  const float* __restrict__ sb,
        float* __restrict__ out)
{
    int b = (blockIdx.x * 1024 + threadIdx.x) >> 5;
    int lane = threadIdx.x & 31;
    if (b >= BGRAPH) return;

    float s = __ldg(mb0 + lane) + g_part[b][lane] + g_part[b][32 + lane] + g_part[b][64 + lane];
    float a0 = fmaxf(s, 0.f);

    float a1 = (lane < 16) ? __ldg(mb1 + lane) : 0.f;
    #pragma unroll
    for (int k = 0; k < 32; k++) {
        float v = __shfl_sync(0xffffffffu, a0, k);
        if (lane < 16) a1 = fmaf(v, __ldg(mw1 + k*16 + lane), a1);
    }
    a1 = fmaxf(a1, 0.f);

    float a2 = (lane < 8) ? __ldg(mb2 + lane) : 0.f;
    #pragma unroll
    for (int k = 0; k < 16; k++) {
        float v = __shfl_sync(0xffffffffu, a1, k);
        if (lane < 8) a2 = fmaf(v, __ldg(mw2 + k*8 + lane), a2);
    }
    a2 = fmaxf(a2, 0.f);

    float a3 = (lane < 4) ? __ldg(mb3 + lane) : 0.f;
    #pragma unroll
    for (int k = 0; k < 8; k++) {
        float v = __shfl_sync(0xffffffffu, a2, k);
        if (lane < 4) a3 = fmaf(v, __ldg(mw3 + k*4 + lane), a3);
    }
    a3 = fmaxf(a3, 0.f);

    float v0 = __shfl_sync(0xffffffffu, a3, 0);
    float v1 = __shfl_sync(0xffffffffu, a3, 1);
    float v2 = __shfl_sync(0xffffffffu, a3, 2);
    float v3 = __shfl_sync(0xffffffffu, a3, 3);
    if (lane == 0) {
        float s4 = __ldg(mb4);
        s4 = fmaf(v0, __ldg(mw4 + 0), s4);
        s4 = fmaf(v1, __ldg(mw4 + 1), s4);
        s4 = fmaf(v2, __ldg(mw4 + 2), s4);
        s4 = fmaf(v3, __ldg(mw4 + 3), s4);
        float f = fmaxf(s4, 0.f);
        float sc = f * __ldg(sw) + __ldg(sb);
        out[b] = 1.f / (1.f + expf(-sc));
    }
}

// ---------------- launch ----------------
extern "C" void kernel_launch(void* const* d_in, const int* in_sizes, int n_in,
                              void* d_out, int out_size) {
    const float* x_i = (const float*)d_in[0];
    const float* x_j = (const float*)d_in[1];
    const float* gw0 = (const float*)d_in[2];  const float* gb0 = (const float*)d_in[3];
    const float* gw1 = (const float*)d_in[4];  const float* gb1 = (const float*)d_in[5];
    const float* gw2 = (const float*)d_in[6];  const float* gb2 = (const float*)d_in[7];
    const float* cw0 = (const float*)d_in[8];  const float* cb0 = (const float*)d_in[9];
    const float* cw1 = (const float*)d_in[10]; const float* cb1 = (const float*)d_in[11];
    const float* cw2 = (const float*)d_in[12]; const float* cb2 = (const float*)d_in[13];
    const float* mw0 = (const float*)d_in[14]; const float* mb0 = (const float*)d_in[15];
    const float* mw1 = (const float*)d_in[16]; const float* mb1 = (const float*)d_in[17];
    const float* mw2 = (const float*)d_in[18]; const float* mb2 = (const float*)d_in[19];
    const float* mw3 = (const float*)d_in[20]; const float* mb3 = (const float*)d_in[21];
    const float* mw4 = (const float*)d_in[22]; const float* mb4 = (const float*)d_in[23];
    const float* sw  = (const float*)d_in[24]; const float* sb  = (const float*)d_in[25];
    const int*   ei  = (const int*)d_in[26];
    const int*   ej  = (const int*)d_in[27];

    cudaFuncSetAttribute(k_fused, cudaFuncAttributeMaxDynamicSharedMemorySize, SMEM_BYTES);

    k_fused<<<dim3(BGRAPH, 2), NT, SMEM_BYTES>>>(x_i, x_j, gw0, gb0, gw1, gb1, gw2, gb2, ei, ej);
    k_headA<<<dim3(BGRAPH, 3), 256>>>(cw0, cb0, cw1, cb1, cw2, cb2, mw0);
    k_headB<<<(BGRAPH*32 + 1023)/1024, 1024>>>(mb0, mw1, mb1, mw2, mb2, mw3, mb3, mw4, mb4,
                                               sw, sb, (float*)d_out);
}